// round 5
// baseline (speedup 1.0000x reference)
#include <cuda_runtime.h>
#include <math.h>

#define BATCH 8
#define NCLS 3
#define H 384
#define W 384
#define HW (H*W)
#define NBC 24
#define JT 4
#define NWARP 12   // 384/32
#define R 4        // rows per k2 block
#define RG (H/R)   // 96 row-groups
#define SENT2 1046529.0f   // 1023^2

// Scratch (device globals, fully overwritten each launch)
__device__ unsigned g_packed[BATCH*HW];   // 3x10-bit column distances per pixel
__device__ float g_psum_bg[NBC*RG];
__device__ float g_psum_fg[NBC*RG];
__device__ float g_pmax_bg[NBC*RG];
__device__ float g_pmax_fg[NBC*RG];

// ---------------------------------------------------------------------------
// k1: per-column 1D distance to nearest (t==c) pixel, all 3 classes, via
// ballot bitmasks. Block = (4-col tile, b), thread = row. Class-2 mask is
// ~(m0|m1) (targets in {0,1,2}). Nearest set bit = AND + clz/ffs with rare
// fallback walk. Distances clamped to 1023 (sentinel), packed 3x10 bits.
// ---------------------------------------------------------------------------
__global__ void __launch_bounds__(384) k1_colscan(const int* __restrict__ targets) {
    __shared__ unsigned sm[NWARP][12];   // [word(row/32)][jj*3+c]
    const int i = threadIdx.x;           // row
    const int lane = i & 31, w = i >> 5;
    const int b = blockIdx.y;
    const int j0 = blockIdx.x * JT;

    int4 ta = *(const int4*)(targets + b*HW + i*W + j0);
    int t[4] = {ta.x, ta.y, ta.z, ta.w};

    unsigned bal[12];
    #pragma unroll
    for (int jj = 0; jj < 4; jj++) {
        unsigned b0 = __ballot_sync(0xffffffffu, t[jj] == 0);
        unsigned b1 = __ballot_sync(0xffffffffu, t[jj] == 1);
        bal[jj*3+0] = b0;
        bal[jj*3+1] = b1;
        bal[jj*3+2] = ~(b0 | b1);
    }
    if (lane == 0) {
        uint4* sp = (uint4*)sm[w];
        sp[0] = make_uint4(bal[0], bal[1], bal[2],  bal[3]);
        sp[1] = make_uint4(bal[4], bal[5], bal[6],  bal[7]);
        sp[2] = make_uint4(bal[8], bal[9], bal[10], bal[11]);
    }
    __syncthreads();

    const unsigned lowmask = 0xffffffffu >> (31 - lane);  // bits 0..lane
    const unsigned himask  = 0xffffffffu << lane;         // bits lane..31
    unsigned outp[4];
    #pragma unroll
    for (int jj = 0; jj < 4; jj++) {
        unsigned gp = 0;
        #pragma unroll
        for (int c = 0; c < 3; c++) {
            const int s = jj*3 + c;
            unsigned mlo = sm[w][s] & lowmask;
            int dfw = 1023;
            if (mlo) dfw = lane - (31 - __clz(mlo));
            else {
                for (int w2 = w - 1; w2 >= 0; --w2) {
                    unsigned m = sm[w2][s];
                    if (m) { dfw = lane + ((w - w2) << 5) - (31 - __clz(m)); break; }
                }
            }
            unsigned mhi = sm[w][s] & himask;
            int dbw = 1023;
            if (mhi) dbw = (__ffs(mhi) - 1) - lane;
            else {
                for (int w2 = w + 1; w2 < NWARP; ++w2) {
                    unsigned m = sm[w2][s];
                    if (m) { dbw = ((w2 - w) << 5) + (__ffs(m) - 1) - lane; break; }
                }
            }
            unsigned g = (unsigned)min(dfw, dbw);
            gp |= g << (10 * c);
        }
        outp[jj] = gp;
    }
    *(uint4*)(g_packed + b*HW + i*W + j0) =
        make_uint4(outp[0], outp[1], outp[2], outp[3]);
}

// ---------------------------------------------------------------------------
// k2: fused row EDT + softmax + partial reductions, R=4 rows per block.
// Double-buffered, sentinel-padded smem (pads never win: 1023^2 > 2*383^2).
// Merged 3-class EDT loop with live per-pixel exit (exact: terms >= r^2).
// Per-thread accumulators across rows; one reduction per block.
// ---------------------------------------------------------------------------
__global__ void __launch_bounds__(384) k2_fused(const float* __restrict__ logits) {
    __shared__ float sh[2][3][3*W];   // [buf][class][pad W | data W | pad W]
    __shared__ float red[NWARP][12];
    const int j = threadIdx.x;
    const int rg = blockIdx.x, b = blockIdx.y;
    const int row0 = rg * R;
    const int lane = j & 31, wid = j >> 5;

    // sentinel pads (written once; never overwritten)
    #pragma unroll
    for (int buf = 0; buf < 2; buf++)
        #pragma unroll
        for (int c = 0; c < 3; c++) {
            sh[buf][c][j]       = SENT2;
            sh[buf][c][2*W + j] = SENT2;
        }

    float accs[6] = {0,0,0,0,0,0};      // p*dbg, p*dfg per class
    float accm[6] = {0,0,0,0,0,0};      // max d2 bg, max d2 fg per class

    unsigned cur = g_packed[b*HW + row0*W + j];
    int buf = 0;

    #pragma unroll
    for (int ri = 0; ri < R; ri++) {
        const int row = row0 + ri;
        float q0 = (float)(cur & 1023u);
        float q1 = (float)((cur >> 10) & 1023u);
        float q2 = (float)((cur >> 20) & 1023u);
        sh[buf][0][W + j] = q0*q0;
        sh[buf][1][W + j] = q1*q1;
        sh[buf][2][W + j] = q2*q2;
        __syncthreads();
        if (ri + 1 < R) cur = g_packed[b*HW + (row+1)*W + j];

        const float* s0 = &sh[buf][0][W];
        const float* s1 = &sh[buf][1][W];
        const float* s2 = &sh[buf][2][W];
        float b0 = s0[j], b1 = s1[j], b2 = s2[j];
        float bestmax = fmaxf(b0, fmaxf(b1, b2));
        float rf = 1.0f;
        int r = 1;
        while (rf*rf < bestmax && r < W) {
            float rr = rf*rf;
            b0 = fminf(b0, fminf(s0[j-r], s0[j+r]) + rr);
            b1 = fminf(b1, fminf(s1[j-r], s1[j+r]) + rr);
            b2 = fminf(b2, fminf(s2[j-r], s2[j+r]) + rr);
            bestmax = fmaxf(b0, fmaxf(b1, b2));
            r++; rf += 1.0f;
        }
        float f0 = fminf(b1, b2);   // fg d2 = min of other classes' bg d2
        float f1 = fminf(b0, b2);
        float f2 = fminf(b0, b1);

        // fast softmax (no max-sub: |logits| small; __expf err ~2e-7)
        const float* lp = logits + (b*3)*HW + row*W + j;
        float e0 = __expf(lp[0]), e1 = __expf(lp[HW]), e2 = __expf(lp[2*HW]);
        float inv = __fdividef(1.0f, e0 + e1 + e2);

        accs[0] += e0*inv * sqrtf(b0);
        accs[1] += e1*inv * sqrtf(b1);
        accs[2] += e2*inv * sqrtf(b2);
        accs[3] += e0*inv * sqrtf(f0);
        accs[4] += e1*inv * sqrtf(f1);
        accs[5] += e2*inv * sqrtf(f2);
        accm[0] = fmaxf(accm[0], b0);
        accm[1] = fmaxf(accm[1], b1);
        accm[2] = fmaxf(accm[2], b2);
        accm[3] = fmaxf(accm[3], f0);
        accm[4] = fmaxf(accm[4], f1);
        accm[5] = fmaxf(accm[5], f2);
        buf ^= 1;
    }

    // warp reduce: 6 sums via shuffles, 6 maxes via redux on positive bits
    #pragma unroll
    for (int off = 16; off; off >>= 1) {
        #pragma unroll
        for (int s = 0; s < 6; s++) accs[s] += __shfl_xor_sync(0xffffffffu, accs[s], off);
    }
    #pragma unroll
    for (int s = 0; s < 6; s++)
        accm[s] = __uint_as_float(__reduce_max_sync(0xffffffffu, __float_as_uint(accm[s])));

    if (lane == 0) {
        #pragma unroll
        for (int s = 0; s < 6; s++) { red[wid][s] = accs[s]; red[wid][6+s] = accm[s]; }
    }
    __syncthreads();
    if (threadIdx.x < 12) {
        int s = threadIdx.x;
        float acc = red[0][s];
        #pragma unroll
        for (int ww = 1; ww < NWARP; ww++)
            acc = (s < 6) ? (acc + red[ww][s]) : fmaxf(acc, red[ww][s]);
        int c = s % 3;
        int idx = (b*3 + c) * RG + rg;
        int grp = s / 3;
        if      (grp == 0) g_psum_bg[idx] = acc;
        else if (grp == 1) g_psum_fg[idx] = acc;
        else if (grp == 2) g_pmax_bg[idx] = sqrtf(acc);   // sqrt(max d2) == max d
        else               g_pmax_fg[idx] = sqrtf(acc);
    }
}

// ---------------------------------------------------------------------------
// k3: final reduce. Warp per (b,c) map; gate = (Mbg < 600) <=> mask nonempty.
// ---------------------------------------------------------------------------
__global__ void k3_final(float* out) {
    const int lane = threadIdx.x & 31, bc = threadIdx.x >> 5;   // 24 warps
    double sbg = 0.0, sfg = 0.0;
    float mbg = 0.0f, mfg = 0.0f;
    for (int r = lane; r < RG; r += 32) {
        sbg += (double)g_psum_bg[bc*RG + r];
        sfg += (double)g_psum_fg[bc*RG + r];
        mbg = fmaxf(mbg, g_pmax_bg[bc*RG + r]);
        mfg = fmaxf(mfg, g_pmax_fg[bc*RG + r]);
    }
    #pragma unroll
    for (int off = 16; off; off >>= 1) {
        sbg += __shfl_xor_sync(0xffffffffu, sbg, off);
        sfg += __shfl_xor_sync(0xffffffffu, sfg, off);
        mbg = fmaxf(mbg, __shfl_xor_sync(0xffffffffu, mbg, off));
        mfg = fmaxf(mfg, __shfl_xor_sync(0xffffffffu, mfg, off));
    }
    __shared__ double cs[24];
    if (lane == 0) {
        double contrib = 0.0;
        if (mbg < 600.0f) {   // mask nonempty (empty-map sentinel d >= 1023)
            contrib = sbg / (double)fmaxf(mbg, 1e-12f)
                    - sfg / (double)fmaxf(mfg, 1e-12f);
        }
        cs[bc] = contrib;
    }
    __syncthreads();
    if (threadIdx.x == 0) {
        double s = 0.0;
        #pragma unroll
        for (int k = 0; k < 24; k++) s += cs[k];
        out[0] = (float)(s / (24.0 * (double)HW));
    }
}

extern "C" void kernel_launch(void* const* d_in, const int* in_sizes, int n_in,
                              void* d_out, int out_size) {
    const float* logits  = (const float*)d_in[0];
    const int*   targets = (const int*)d_in[1];

    dim3 g1(W / JT, BATCH);
    k1_colscan<<<g1, H>>>(targets);
    dim3 g2(RG, BATCH);
    k2_fused<<<g2, W>>>(logits);
    k3_final<<<1, 24 * 32>>>((float*)d_out);
}

// round 6
// speedup vs baseline: 1.1679x; 1.1679x over previous
#include <cuda_runtime.h>
#include <math.h>

#define BATCH 8
#define NCLS 3
#define H 384
#define W 384
#define HW (H*W)
#define NBC 24
#define JT 4
#define NWARP 12   // 384/32
#define R 8        // rows per k2 block
#define RG (H/R)   // 48 row-groups
#define SENT2 1046529.0f   // 1023^2

// Scratch (device globals, fully overwritten each launch)
__device__ unsigned g_packed[BATCH*HW];   // 3x10-bit column distances per pixel
__device__ float g_psum_bg[NBC*RG];
__device__ float g_psum_fg[NBC*RG];
__device__ float g_pmax_bg[NBC*RG];
__device__ float g_pmax_fg[NBC*RG];

// ---------------------------------------------------------------------------
// k1: per-column 1D distance to nearest (t==c) pixel, all 3 classes, via
// ballot bitmasks. Block = (4-col tile, b), thread = row. Class-2 mask is
// ~(m0|m1) (targets in {0,1,2}). Nearest set bit = AND + clz/ffs with rare
// fallback walk. Distances clamped to 1023 (sentinel), packed 3x10 bits.
// ---------------------------------------------------------------------------
__global__ void __launch_bounds__(384) k1_colscan(const int* __restrict__ targets) {
    __shared__ unsigned sm[NWARP][12];   // [word(row/32)][jj*3+c]
    const int i = threadIdx.x;           // row
    const int lane = i & 31, w = i >> 5;
    const int b = blockIdx.y;
    const int j0 = blockIdx.x * JT;

    int4 ta = *(const int4*)(targets + b*HW + i*W + j0);
    int t[4] = {ta.x, ta.y, ta.z, ta.w};

    unsigned bal[12];
    #pragma unroll
    for (int jj = 0; jj < 4; jj++) {
        unsigned b0 = __ballot_sync(0xffffffffu, t[jj] == 0);
        unsigned b1 = __ballot_sync(0xffffffffu, t[jj] == 1);
        bal[jj*3+0] = b0;
        bal[jj*3+1] = b1;
        bal[jj*3+2] = ~(b0 | b1);
    }
    if (lane == 0) {
        uint4* sp = (uint4*)sm[w];
        sp[0] = make_uint4(bal[0], bal[1], bal[2],  bal[3]);
        sp[1] = make_uint4(bal[4], bal[5], bal[6],  bal[7]);
        sp[2] = make_uint4(bal[8], bal[9], bal[10], bal[11]);
    }
    __syncthreads();

    const unsigned lowmask = 0xffffffffu >> (31 - lane);  // bits 0..lane
    const unsigned himask  = 0xffffffffu << lane;         // bits lane..31
    unsigned outp[4];
    #pragma unroll
    for (int jj = 0; jj < 4; jj++) {
        unsigned gp = 0;
        #pragma unroll
        for (int c = 0; c < 3; c++) {
            const int s = jj*3 + c;
            unsigned mlo = sm[w][s] & lowmask;
            int dfw = 1023;
            if (mlo) dfw = lane - (31 - __clz(mlo));
            else {
                for (int w2 = w - 1; w2 >= 0; --w2) {
                    unsigned m = sm[w2][s];
                    if (m) { dfw = lane + ((w - w2) << 5) - (31 - __clz(m)); break; }
                }
            }
            unsigned mhi = sm[w][s] & himask;
            int dbw = 1023;
            if (mhi) dbw = (__ffs(mhi) - 1) - lane;
            else {
                for (int w2 = w + 1; w2 < NWARP; ++w2) {
                    unsigned m = sm[w2][s];
                    if (m) { dbw = ((w2 - w) << 5) + (__ffs(m) - 1) - lane; break; }
                }
            }
            unsigned g = (unsigned)min(dfw, dbw);
            gp |= g << (10 * c);
        }
        outp[jj] = gp;
    }
    *(uint4*)(g_packed + b*HW + i*W + j0) =
        make_uint4(outp[0], outp[1], outp[2], outp[3]);
}

// ---------------------------------------------------------------------------
// k2: fused row EDT + softmax + partial reductions, R=8 rows per block.
// MUFU-minimized: 3 sqrt (fg via min of bg sqrts — sqrt is monotone),
// 2 exp (softmax normalized by class 2), 1 fast reciprocal.
// Double-buffered, sentinel-padded smem; merged 3-class EDT loop with
// live per-pixel exit (exact: terms >= r^2).
// ---------------------------------------------------------------------------
__global__ void __launch_bounds__(384) k2_fused(const float* __restrict__ logits) {
    __shared__ float sh[2][3][3*W];   // [buf][class][pad W | data W | pad W]
    __shared__ float red[NWARP][12];
    const int j = threadIdx.x;
    const int rg = blockIdx.x, b = blockIdx.y;
    const int row0 = rg * R;
    const int lane = j & 31, wid = j >> 5;

    // sentinel pads (written once; never overwritten)
    #pragma unroll
    for (int buf = 0; buf < 2; buf++)
        #pragma unroll
        for (int c = 0; c < 3; c++) {
            sh[buf][c][j]       = SENT2;
            sh[buf][c][2*W + j] = SENT2;
        }

    float accs[6] = {0,0,0,0,0,0};      // p*dbg, p*dfg per class
    float accm[6] = {0,0,0,0,0,0};      // max d2 bg, max d2 fg per class

    unsigned cur = g_packed[b*HW + row0*W + j];
    int buf = 0;

    #pragma unroll
    for (int ri = 0; ri < R; ri++) {
        const int row = row0 + ri;
        float q0 = (float)(cur & 1023u);
        float q1 = (float)((cur >> 10) & 1023u);
        float q2 = (float)((cur >> 20) & 1023u);
        sh[buf][0][W + j] = q0*q0;
        sh[buf][1][W + j] = q1*q1;
        sh[buf][2][W + j] = q2*q2;
        __syncthreads();
        if (ri + 1 < R) cur = g_packed[b*HW + (row+1)*W + j];

        const float* s0 = &sh[buf][0][W];
        const float* s1 = &sh[buf][1][W];
        const float* s2 = &sh[buf][2][W];
        float b0 = s0[j], b1 = s1[j], b2 = s2[j];
        float bestmax = fmaxf(b0, fmaxf(b1, b2));
        float rf = 1.0f;
        int r = 1;
        while (rf*rf < bestmax && r < W) {
            float rr = rf*rf;
            b0 = fminf(b0, fminf(s0[j-r], s0[j+r]) + rr);
            b1 = fminf(b1, fminf(s1[j-r], s1[j+r]) + rr);
            b2 = fminf(b2, fminf(s2[j-r], s2[j+r]) + rr);
            bestmax = fmaxf(b0, fmaxf(b1, b2));
            r++; rf += 1.0f;
        }
        // bg sqrts once; fg sqrts = mins of bg sqrts (sqrt monotone)
        float sb0 = sqrtf(b0), sb1 = sqrtf(b1), sb2 = sqrtf(b2);
        float sf0 = fminf(sb1, sb2);
        float sf1 = fminf(sb0, sb2);
        float sf2 = fminf(sb0, sb1);

        // softmax normalized by class 2: e2 = 1 (identical values, 2 MUFU)
        const float* lp = logits + (b*3)*HW + row*W + j;
        float l2v = lp[2*HW];
        float e0 = __expf(lp[0] - l2v), e1 = __expf(lp[HW] - l2v);
        float inv = __fdividef(1.0f, e0 + e1 + 1.0f);
        float p0 = e0*inv, p1 = e1*inv, p2 = inv;

        accs[0] += p0 * sb0;
        accs[1] += p1 * sb1;
        accs[2] += p2 * sb2;
        accs[3] += p0 * sf0;
        accs[4] += p1 * sf1;
        accs[5] += p2 * sf2;
        accm[0] = fmaxf(accm[0], b0);
        accm[1] = fmaxf(accm[1], b1);
        accm[2] = fmaxf(accm[2], b2);
        accm[3] = fmaxf(accm[3], fminf(b1, b2));
        accm[4] = fmaxf(accm[4], fminf(b0, b2));
        accm[5] = fmaxf(accm[5], fminf(b0, b1));
        buf ^= 1;
    }

    // warp reduce: 6 sums via shuffles, 6 maxes via redux on positive bits
    #pragma unroll
    for (int off = 16; off; off >>= 1) {
        #pragma unroll
        for (int s = 0; s < 6; s++) accs[s] += __shfl_xor_sync(0xffffffffu, accs[s], off);
    }
    #pragma unroll
    for (int s = 0; s < 6; s++)
        accm[s] = __uint_as_float(__reduce_max_sync(0xffffffffu, __float_as_uint(accm[s])));

    if (lane == 0) {
        #pragma unroll
        for (int s = 0; s < 6; s++) { red[wid][s] = accs[s]; red[wid][6+s] = accm[s]; }
    }
    __syncthreads();
    if (threadIdx.x < 12) {
        int s = threadIdx.x;
        float acc = red[0][s];
        #pragma unroll
        for (int ww = 1; ww < NWARP; ww++)
            acc = (s < 6) ? (acc + red[ww][s]) : fmaxf(acc, red[ww][s]);
        int c = s % 3;
        int idx = (b*3 + c) * RG + rg;
        int grp = s / 3;
        if      (grp == 0) g_psum_bg[idx] = acc;
        else if (grp == 1) g_psum_fg[idx] = acc;
        else if (grp == 2) g_pmax_bg[idx] = sqrtf(acc);   // sqrt(max d2) == max d
        else               g_pmax_fg[idx] = sqrtf(acc);
    }
}

// ---------------------------------------------------------------------------
// k3: final reduce. Warp per (b,c) map; gate = (Mbg < 600) <=> mask nonempty.
// ---------------------------------------------------------------------------
__global__ void k3_final(float* out) {
    const int lane = threadIdx.x & 31, bc = threadIdx.x >> 5;   // 24 warps
    double sbg = 0.0, sfg = 0.0;
    float mbg = 0.0f, mfg = 0.0f;
    for (int r = lane; r < RG; r += 32) {
        sbg += (double)g_psum_bg[bc*RG + r];
        sfg += (double)g_psum_fg[bc*RG + r];
        mbg = fmaxf(mbg, g_pmax_bg[bc*RG + r]);
        mfg = fmaxf(mfg, g_pmax_fg[bc*RG + r]);
    }
    #pragma unroll
    for (int off = 16; off; off >>= 1) {
        sbg += __shfl_xor_sync(0xffffffffu, sbg, off);
        sfg += __shfl_xor_sync(0xffffffffu, sfg, off);
        mbg = fmaxf(mbg, __shfl_xor_sync(0xffffffffu, mbg, off));
        mfg = fmaxf(mfg, __shfl_xor_sync(0xffffffffu, mfg, off));
    }
    __shared__ double cs[24];
    if (lane == 0) {
        double contrib = 0.0;
        if (mbg < 600.0f) {   // mask nonempty (empty-map sentinel d >= 1023)
            contrib = sbg / (double)fmaxf(mbg, 1e-12f)
                    - sfg / (double)fmaxf(mfg, 1e-12f);
        }
        cs[bc] = contrib;
    }
    __syncthreads();
    if (threadIdx.x == 0) {
        double s = 0.0;
        #pragma unroll
        for (int k = 0; k < 24; k++) s += cs[k];
        out[0] = (float)(s / (24.0 * (double)HW));
    }
}

extern "C" void kernel_launch(void* const* d_in, const int* in_sizes, int n_in,
                              void* d_out, int out_size) {
    const float* logits  = (const float*)d_in[0];
    const int*   targets = (const int*)d_in[1];

    dim3 g1(W / JT, BATCH);
    k1_colscan<<<g1, H>>>(targets);
    dim3 g2(RG, BATCH);
    k2_fused<<<g2, W>>>(logits);
    k3_final<<<1, 24 * 32>>>((float*)d_out);
}

// round 7
// speedup vs baseline: 1.2541x; 1.0738x over previous
#include <cuda_runtime.h>
#include <math.h>

#define BATCH 8
#define NCLS 3
#define H 384
#define W 384
#define HW (H*W)
#define NBC 24
#define JT 4
#define NWARP 12   // 384/32
#define NWORD 12   // H/32 mask words per column
#define R 8        // rows per k2 block
#define RG (H/R)   // 48 row-groups
#define SENT2 1046529.0f   // 1023^2

// Scratch (device globals, fully overwritten each launch)
// layout: [b][c][word][j]
__device__ unsigned g_mask[BATCH*3*NWORD*W];
__device__ int      g_pn  [BATCH*3*NWORD*W];   // low16 = prev row (s16), high16 = next row (s16)
__device__ float g_psum_bg[NBC*RG];
__device__ float g_psum_fg[NBC*RG];
__device__ float g_pmax_bg[NBC*RG];
__device__ float g_pmax_fg[NBC*RG];

// ---------------------------------------------------------------------------
// k1: build per-column class bitmasks via ballot (thread = row, 4-col tile)
// and per (col,class,word) nearest-set-row below/above (prev/next, s16 pair).
// No distance math here — k2 derives distances from (word, prev, next).
// ---------------------------------------------------------------------------
__global__ void __launch_bounds__(384) k1_masks(const int* __restrict__ targets) {
    __shared__ unsigned sm[NWORD][12];   // [word][jj*3+c]
    const int i = threadIdx.x;           // row
    const int lane = i & 31, w = i >> 5;
    const int b = blockIdx.y;
    const int j0 = blockIdx.x * JT;

    int4 ta = *(const int4*)(targets + b*HW + i*W + j0);
    int t[4] = {ta.x, ta.y, ta.z, ta.w};

    unsigned bal[12];
    #pragma unroll
    for (int jj = 0; jj < 4; jj++) {
        unsigned b0 = __ballot_sync(0xffffffffu, t[jj] == 0);
        unsigned b1 = __ballot_sync(0xffffffffu, t[jj] == 1);
        bal[jj*3+0] = b0;
        bal[jj*3+1] = b1;
        bal[jj*3+2] = ~(b0 | b1);
    }
    if (lane == 0) {
        #pragma unroll
        for (int c = 0; c < 3; c++) {
            *(uint4*)&g_mask[((b*3 + c)*NWORD + w)*W + j0] =
                make_uint4(bal[0*3+c], bal[1*3+c], bal[2*3+c], bal[3*3+c]);
        }
        uint4* sp = (uint4*)sm[w];
        sp[0] = make_uint4(bal[0], bal[1], bal[2],  bal[3]);
        sp[1] = make_uint4(bal[4], bal[5], bal[6],  bal[7]);
        sp[2] = make_uint4(bal[8], bal[9], bal[10], bal[11]);
    }
    __syncthreads();

    if (threadIdx.x < 144) {   // one thread per (c, jj, word)
        const int tt = threadIdx.x;
        const int c = tt / 48, r48 = tt % 48;
        const int jj = r48 / NWORD, w2 = r48 % NWORD;
        const int s = jj*3 + c;
        int prev = -2000;
        for (int ww = w2 - 1; ww >= 0; --ww) {
            unsigned m = sm[ww][s];
            if (m) { prev = ww*32 + 31 - __clz(m); break; }
        }
        int next = 3000;
        for (int ww = w2 + 1; ww < NWORD; ++ww) {
            unsigned m = sm[ww][s];
            if (m) { next = ww*32 + __ffs(m) - 1; break; }
        }
        g_pn[((b*3 + c)*NWORD + w2)*W + j0 + jj] =
            (int)(((unsigned)(prev & 0xffff)) | ((unsigned)next << 16));
    }
}

// ---------------------------------------------------------------------------
// k2: fused column-distance derivation + row EDT + softmax + partial
// reductions, R=8 rows per block (all rows share one mask word: 8 | 32).
// Per thread: 6 coalesced loads once, then branch-free clz/ffs per row.
// MUFU-minimized (3 sqrt, 2 exp, 1 rcp). Sentinel-padded smem EDT with
// live per-pixel exit (exact: terms >= r^2).
// ---------------------------------------------------------------------------
__global__ void __launch_bounds__(384) k2_fused(const float* __restrict__ logits) {
    __shared__ float sh[2][3][3*W];   // [buf][class][pad W | data W | pad W]
    __shared__ float red[NWARP][12];
    const int j = threadIdx.x;
    const int rg = blockIdx.x, b = blockIdx.y;
    const int row0 = rg * R;
    const int w = row0 >> 5;          // single mask word for all 8 rows
    const int lane = j & 31, wid = j >> 5;

    // sentinel pads (written once; never overwritten)
    #pragma unroll
    for (int buf = 0; buf < 2; buf++)
        #pragma unroll
        for (int c = 0; c < 3; c++) {
            sh[buf][c][j]       = SENT2;
            sh[buf][c][2*W + j] = SENT2;
        }

    const int mbase = ((b*3)*NWORD + w)*W + j;   // class stride = NWORD*W
    unsigned mw[3];
    int prv[3], nxt[3];
    #pragma unroll
    for (int c = 0; c < 3; c++) {
        mw[c] = g_mask[mbase + c*NWORD*W];
        int pn = g_pn[mbase + c*NWORD*W];
        prv[c] = (int)(short)(pn & 0xffff);
        nxt[c] = pn >> 16;
    }

    float accs[6] = {0,0,0,0,0,0};      // p*dbg, p*dfg per class
    float accm[6] = {0,0,0,0,0,0};      // max d2 bg, max d2 fg per class
    int buf = 0;

    #pragma unroll
    for (int ri = 0; ri < R; ri++) {
        const int row = row0 + ri;
        const int lr = row & 31;                         // uniform
        const unsigned lowmask = 0xffffffffu >> (31 - lr);
        const unsigned himask  = 0xffffffffu << lr;
        #pragma unroll
        for (int c = 0; c < 3; c++) {
            unsigned mlo = mw[c] & lowmask;
            int dfw = mlo ? (lr + __clz(mlo) - 31) : (row - prv[c]);
            unsigned mhi = mw[c] & himask;
            int dbw = mhi ? (__ffs(mhi) - 1 - lr) : (nxt[c] - row);
            int g = min(min(dfw, dbw), 1023);
            sh[buf][c][W + j] = (float)(g * g);
        }
        __syncthreads();

        const float* s0 = &sh[buf][0][W];
        const float* s1 = &sh[buf][1][W];
        const float* s2 = &sh[buf][2][W];
        float b0 = s0[j], b1 = s1[j], b2 = s2[j];
        float bestmax = fmaxf(b0, fmaxf(b1, b2));
        float rf = 1.0f;
        int r = 1;
        while (rf*rf < bestmax && r < W) {
            float rr = rf*rf;
            b0 = fminf(b0, fminf(s0[j-r], s0[j+r]) + rr);
            b1 = fminf(b1, fminf(s1[j-r], s1[j+r]) + rr);
            b2 = fminf(b2, fminf(s2[j-r], s2[j+r]) + rr);
            bestmax = fmaxf(b0, fmaxf(b1, b2));
            r++; rf += 1.0f;
        }
        // bg sqrts once; fg sqrts = mins of bg sqrts (sqrt monotone)
        float sb0 = sqrtf(b0), sb1 = sqrtf(b1), sb2 = sqrtf(b2);
        float sf0 = fminf(sb1, sb2);
        float sf1 = fminf(sb0, sb2);
        float sf2 = fminf(sb0, sb1);

        // softmax normalized by class 2: e2 = 1 (identical values, 2 MUFU)
        const float* lp = logits + (b*3)*HW + row*W + j;
        float l2v = lp[2*HW];
        float e0 = __expf(lp[0] - l2v), e1 = __expf(lp[HW] - l2v);
        float inv = __fdividef(1.0f, e0 + e1 + 1.0f);
        float p0 = e0*inv, p1 = e1*inv, p2 = inv;

        accs[0] += p0 * sb0;
        accs[1] += p1 * sb1;
        accs[2] += p2 * sb2;
        accs[3] += p0 * sf0;
        accs[4] += p1 * sf1;
        accs[5] += p2 * sf2;
        accm[0] = fmaxf(accm[0], b0);
        accm[1] = fmaxf(accm[1], b1);
        accm[2] = fmaxf(accm[2], b2);
        accm[3] = fmaxf(accm[3], fminf(b1, b2));
        accm[4] = fmaxf(accm[4], fminf(b0, b2));
        accm[5] = fmaxf(accm[5], fminf(b0, b1));
        buf ^= 1;
    }

    // warp reduce: 6 sums via shuffles, 6 maxes via redux on positive bits
    #pragma unroll
    for (int off = 16; off; off >>= 1) {
        #pragma unroll
        for (int s = 0; s < 6; s++) accs[s] += __shfl_xor_sync(0xffffffffu, accs[s], off);
    }
    #pragma unroll
    for (int s = 0; s < 6; s++)
        accm[s] = __uint_as_float(__reduce_max_sync(0xffffffffu, __float_as_uint(accm[s])));

    if (lane == 0) {
        #pragma unroll
        for (int s = 0; s < 6; s++) { red[wid][s] = accs[s]; red[wid][6+s] = accm[s]; }
    }
    __syncthreads();
    if (threadIdx.x < 12) {
        int s = threadIdx.x;
        float acc = red[0][s];
        #pragma unroll
        for (int ww = 1; ww < NWARP; ww++)
            acc = (s < 6) ? (acc + red[ww][s]) : fmaxf(acc, red[ww][s]);
        int c = s % 3;
        int idx = (b*3 + c) * RG + rg;
        int grp = s / 3;
        if      (grp == 0) g_psum_bg[idx] = acc;
        else if (grp == 1) g_psum_fg[idx] = acc;
        else if (grp == 2) g_pmax_bg[idx] = sqrtf(acc);   // sqrt(max d2) == max d
        else               g_pmax_fg[idx] = sqrtf(acc);
    }
}

// ---------------------------------------------------------------------------
// k3: final reduce. Warp per (b,c) map; gate = (Mbg < 600) <=> mask nonempty.
// ---------------------------------------------------------------------------
__global__ void k3_final(float* out) {
    const int lane = threadIdx.x & 31, bc = threadIdx.x >> 5;   // 24 warps
    double sbg = 0.0, sfg = 0.0;
    float mbg = 0.0f, mfg = 0.0f;
    for (int r = lane; r < RG; r += 32) {
        sbg += (double)g_psum_bg[bc*RG + r];
        sfg += (double)g_psum_fg[bc*RG + r];
        mbg = fmaxf(mbg, g_pmax_bg[bc*RG + r]);
        mfg = fmaxf(mfg, g_pmax_fg[bc*RG + r]);
    }
    #pragma unroll
    for (int off = 16; off; off >>= 1) {
        sbg += __shfl_xor_sync(0xffffffffu, sbg, off);
        sfg += __shfl_xor_sync(0xffffffffu, sfg, off);
        mbg = fmaxf(mbg, __shfl_xor_sync(0xffffffffu, mbg, off));
        mfg = fmaxf(mfg, __shfl_xor_sync(0xffffffffu, mfg, off));
    }
    __shared__ double cs[24];
    if (lane == 0) {
        double contrib = 0.0;
        if (mbg < 600.0f) {   // mask nonempty (empty-map sentinel d >= 1023)
            contrib = sbg / (double)fmaxf(mbg, 1e-12f)
                    - sfg / (double)fmaxf(mfg, 1e-12f);
        }
        cs[bc] = contrib;
    }
    __syncthreads();
    if (threadIdx.x == 0) {
        double s = 0.0;
        #pragma unroll
        for (int k = 0; k < 24; k++) s += cs[k];
        out[0] = (float)(s / (24.0 * (double)HW));
    }
}

extern "C" void kernel_launch(void* const* d_in, const int* in_sizes, int n_in,
                              void* d_out, int out_size) {
    const float* logits  = (const float*)d_in[0];
    const int*   targets = (const int*)d_in[1];

    dim3 g1(W / JT, BATCH);
    k1_masks<<<g1, H>>>(targets);
    dim3 g2(RG, BATCH);
    k2_fused<<<g2, W>>>(logits);
    k3_final<<<1, 24 * 32>>>((float*)d_out);
}

// round 8
// speedup vs baseline: 1.2554x; 1.0010x over previous
#include <cuda_runtime.h>
#include <math.h>

#define BATCH 8
#define NCLS 3
#define H 384
#define W 384
#define HW (H*W)
#define NBC 24
#define JT 8
#define NWARP 12   // 384/32
#define NWORD 12   // H/32 mask words per column
#define R 8        // rows per k2 block
#define RG (H/R)   // 48 row-groups
#define P 32       // fast-path EDT pad/radius
#define SENT2 1046529.0f   // 1023^2

// Scratch (device globals, fully overwritten each launch)
// layout: [b][c][word][j]
__device__ unsigned g_mask[BATCH*3*NWORD*W];
__device__ int      g_pn  [BATCH*3*NWORD*W];   // low16 = prev row (s16), high16 = next row (s16)
__device__ float g_psum_bg[NBC*RG];
__device__ float g_psum_fg[NBC*RG];
__device__ float g_pmax_bg[NBC*RG];
__device__ float g_pmax_fg[NBC*RG];

// ---------------------------------------------------------------------------
// k1: build per-column class bitmasks via ballot (thread = row, 8-col tile,
// MLP=2 on the transposed loads) and per (col,class,word) nearest-set-row
// below/above (prev/next, s16 pair). k2 derives distances from these.
// ---------------------------------------------------------------------------
__global__ void __launch_bounds__(384) k1_masks(const int* __restrict__ targets) {
    __shared__ unsigned sm[NWORD][24];   // [word][jj*3+c]
    const int i = threadIdx.x;           // row
    const int lane = i & 31, w = i >> 5;
    const int b = blockIdx.y;
    const int j0 = blockIdx.x * JT;

    const int4* tp = (const int4*)(targets + b*HW + i*W + j0);
    int4 ta = tp[0], tb = tp[1];         // two independent LDG.128
    int t[8] = {ta.x, ta.y, ta.z, ta.w, tb.x, tb.y, tb.z, tb.w};

    unsigned bal[24];
    #pragma unroll
    for (int jj = 0; jj < 8; jj++) {
        unsigned b0 = __ballot_sync(0xffffffffu, t[jj] == 0);
        unsigned b1 = __ballot_sync(0xffffffffu, t[jj] == 1);
        bal[jj*3+0] = b0;
        bal[jj*3+1] = b1;
        bal[jj*3+2] = ~(b0 | b1);
    }
    if (lane == 0) {
        #pragma unroll
        for (int c = 0; c < 3; c++) {
            uint4* gm = (uint4*)&g_mask[((b*3 + c)*NWORD + w)*W + j0];
            gm[0] = make_uint4(bal[0*3+c], bal[1*3+c], bal[2*3+c], bal[3*3+c]);
            gm[1] = make_uint4(bal[4*3+c], bal[5*3+c], bal[6*3+c], bal[7*3+c]);
        }
        uint4* sp = (uint4*)sm[w];
        #pragma unroll
        for (int q = 0; q < 6; q++)
            sp[q] = make_uint4(bal[q*4+0], bal[q*4+1], bal[q*4+2], bal[q*4+3]);
    }
    __syncthreads();

    if (threadIdx.x < 288) {   // one thread per (c, jj, word)
        const int tt = threadIdx.x;
        const int c = tt / 96, r96 = tt % 96;
        const int jj = r96 / NWORD, w2 = r96 % NWORD;
        const int s = jj*3 + c;
        int prev = -2000;
        for (int ww = w2 - 1; ww >= 0; --ww) {
            unsigned m = sm[ww][s];
            if (m) { prev = ww*32 + 31 - __clz(m); break; }
        }
        int next = 3000;
        for (int ww = w2 + 1; ww < NWORD; ++ww) {
            unsigned m = sm[ww][s];
            if (m) { next = ww*32 + __ffs(m) - 1; break; }
        }
        g_pn[((b*3 + c)*NWORD + w2)*W + j0 + jj] =
            (int)(((unsigned)(prev & 0xffff)) | ((unsigned)next << 16));
    }
}

// ---------------------------------------------------------------------------
// k2: single-barrier fused kernel. Phase 1: derive all 24 g^2 (3 classes x
// 8 rows, which share one mask word since 8 | 32) into padded smem. One
// __syncthreads. Phase 2: per-row independent EDT walks (fast path r <= P
// against SENT2 pads that provably never win; exact bounds-checked fallback
// for r > P), MUFU-minimized epilogue, register accumulators, one reduction.
// ---------------------------------------------------------------------------
__global__ void __launch_bounds__(384) k2_fused(const float* __restrict__ logits) {
    __shared__ float sh[3][R][W + 2*P];
    __shared__ float red[NWARP][12];
    const int j = threadIdx.x;
    const int rg = blockIdx.x, b = blockIdx.y;
    const int row0 = rg * R;
    const int w = row0 >> 5;          // single mask word for all 8 rows
    const int lane = j & 31, wid = j >> 5;

    // sentinel pads
    #pragma unroll
    for (int c = 0; c < 3; c++)
        #pragma unroll
        for (int ri = 0; ri < R; ri++) {
            if (j < 2*P) {
                int side = (j < P) ? j : (W + j);
                sh[c][ri][side] = SENT2;
            }
        }

    const int mbase = ((b*3)*NWORD + w)*W + j;   // class stride = NWORD*W
    unsigned mw[3];
    int prv[3], nxt[3];
    #pragma unroll
    for (int c = 0; c < 3; c++) {
        mw[c] = g_mask[mbase + c*NWORD*W];
        int pn = g_pn[mbase + c*NWORD*W];
        prv[c] = (int)(short)(pn & 0xffff);
        nxt[c] = pn >> 16;
    }

    // phase 1: all 24 column distances -> smem
    #pragma unroll
    for (int ri = 0; ri < R; ri++) {
        const int row = row0 + ri;
        const int lr = row & 31;                         // uniform
        const unsigned lowmask = 0xffffffffu >> (31 - lr);
        const unsigned himask  = 0xffffffffu << lr;
        #pragma unroll
        for (int c = 0; c < 3; c++) {
            unsigned mlo = mw[c] & lowmask;
            int dfw = mlo ? (lr + __clz(mlo) - 31) : (row - prv[c]);
            unsigned mhi = mw[c] & himask;
            int dbw = mhi ? (__ffs(mhi) - 1 - lr) : (nxt[c] - row);
            int g = min(min(dfw, dbw), 1023);
            sh[c][ri][P + j] = (float)(g * g);
        }
    }
    __syncthreads();   // the only block barrier before the reduction

    float accs[6] = {0,0,0,0,0,0};      // p*dbg, p*dfg per class
    float accm[6] = {0,0,0,0,0,0};      // max d2 bg, max d2 fg per class

    #pragma unroll
    for (int ri = 0; ri < R; ri++) {
        const int row = row0 + ri;
        const float* s0 = &sh[0][ri][P];
        const float* s1 = &sh[1][ri][P];
        const float* s2 = &sh[2][ri][P];
        float b0 = s0[j], b1 = s1[j], b2 = s2[j];
        float bestmax = fmaxf(b0, fmaxf(b1, b2));
        float rf = 1.0f;
        int r = 1;
        // fast path: pads absorb out-of-range reads (SENT2 never wins)
        while (rf*rf < bestmax && r <= P) {
            float rr = rf*rf;
            b0 = fminf(b0, fminf(s0[j-r], s0[j+r]) + rr);
            b1 = fminf(b1, fminf(s1[j-r], s1[j+r]) + rr);
            b2 = fminf(b2, fminf(s2[j-r], s2[j+r]) + rr);
            bestmax = fmaxf(b0, fmaxf(b1, b2));
            r++; rf += 1.0f;
        }
        // exact cold fallback (only reachable when a class is absent from
        // >=P nearby columns; bounds-checked)
        while (rf*rf < bestmax && r < W) {
            float rr = rf*rf;
            int lo = j - r, hi = j + r;
            if (lo >= 0) {
                b0 = fminf(b0, s0[lo] + rr);
                b1 = fminf(b1, s1[lo] + rr);
                b2 = fminf(b2, s2[lo] + rr);
            }
            if (hi < W) {
                b0 = fminf(b0, s0[hi] + rr);
                b1 = fminf(b1, s1[hi] + rr);
                b2 = fminf(b2, s2[hi] + rr);
            }
            bestmax = fmaxf(b0, fmaxf(b1, b2));
            r++; rf += 1.0f;
        }
        // bg sqrts once; fg sqrts = mins of bg sqrts (sqrt monotone)
        float sb0 = sqrtf(b0), sb1 = sqrtf(b1), sb2 = sqrtf(b2);
        float sf0 = fminf(sb1, sb2);
        float sf1 = fminf(sb0, sb2);
        float sf2 = fminf(sb0, sb1);

        // softmax normalized by class 2: e2 = 1 (identical values, 2 MUFU)
        const float* lp = logits + (b*3)*HW + row*W + j;
        float l2v = lp[2*HW];
        float e0 = __expf(lp[0] - l2v), e1 = __expf(lp[HW] - l2v);
        float inv = __fdividef(1.0f, e0 + e1 + 1.0f);
        float p0 = e0*inv, p1 = e1*inv, p2 = inv;

        accs[0] += p0 * sb0;
        accs[1] += p1 * sb1;
        accs[2] += p2 * sb2;
        accs[3] += p0 * sf0;
        accs[4] += p1 * sf1;
        accs[5] += p2 * sf2;
        accm[0] = fmaxf(accm[0], b0);
        accm[1] = fmaxf(accm[1], b1);
        accm[2] = fmaxf(accm[2], b2);
        accm[3] = fmaxf(accm[3], fminf(b1, b2));
        accm[4] = fmaxf(accm[4], fminf(b0, b2));
        accm[5] = fmaxf(accm[5], fminf(b0, b1));
    }

    // warp reduce: 6 sums via shuffles, 6 maxes via redux on positive bits
    #pragma unroll
    for (int off = 16; off; off >>= 1) {
        #pragma unroll
        for (int s = 0; s < 6; s++) accs[s] += __shfl_xor_sync(0xffffffffu, accs[s], off);
    }
    #pragma unroll
    for (int s = 0; s < 6; s++)
        accm[s] = __uint_as_float(__reduce_max_sync(0xffffffffu, __float_as_uint(accm[s])));

    if (lane == 0) {
        #pragma unroll
        for (int s = 0; s < 6; s++) { red[wid][s] = accs[s]; red[wid][6+s] = accm[s]; }
    }
    __syncthreads();
    if (threadIdx.x < 12) {
        int s = threadIdx.x;
        float acc = red[0][s];
        #pragma unroll
        for (int ww = 1; ww < NWARP; ww++)
            acc = (s < 6) ? (acc + red[ww][s]) : fmaxf(acc, red[ww][s]);
        int c = s % 3;
        int idx = (b*3 + c) * RG + rg;
        int grp = s / 3;
        if      (grp == 0) g_psum_bg[idx] = acc;
        else if (grp == 1) g_psum_fg[idx] = acc;
        else if (grp == 2) g_pmax_bg[idx] = sqrtf(acc);   // sqrt(max d2) == max d
        else               g_pmax_fg[idx] = sqrtf(acc);
    }
}

// ---------------------------------------------------------------------------
// k3: final reduce. Warp per (b,c) map; gate = (Mbg < 600) <=> mask nonempty.
// ---------------------------------------------------------------------------
__global__ void k3_final(float* out) {
    const int lane = threadIdx.x & 31, bc = threadIdx.x >> 5;   // 24 warps
    double sbg = 0.0, sfg = 0.0;
    float mbg = 0.0f, mfg = 0.0f;
    for (int r = lane; r < RG; r += 32) {
        sbg += (double)g_psum_bg[bc*RG + r];
        sfg += (double)g_psum_fg[bc*RG + r];
        mbg = fmaxf(mbg, g_pmax_bg[bc*RG + r]);
        mfg = fmaxf(mfg, g_pmax_fg[bc*RG + r]);
    }
    #pragma unroll
    for (int off = 16; off; off >>= 1) {
        sbg += __shfl_xor_sync(0xffffffffu, sbg, off);
        sfg += __shfl_xor_sync(0xffffffffu, sfg, off);
        mbg = fmaxf(mbg, __shfl_xor_sync(0xffffffffu, mbg, off));
        mfg = fmaxf(mfg, __shfl_xor_sync(0xffffffffu, mfg, off));
    }
    __shared__ double cs[24];
    if (lane == 0) {
        double contrib = 0.0;
        if (mbg < 600.0f) {   // mask nonempty (empty-map sentinel d >= 1023)
            contrib = sbg / (double)fmaxf(mbg, 1e-12f)
                    - sfg / (double)fmaxf(mfg, 1e-12f);
        }
        cs[bc] = contrib;
    }
    __syncthreads();
    if (threadIdx.x == 0) {
        double s = 0.0;
        #pragma unroll
        for (int k = 0; k < 24; k++) s += cs[k];
        out[0] = (float)(s / (24.0 * (double)HW));
    }
}

extern "C" void kernel_launch(void* const* d_in, const int* in_sizes, int n_in,
                              void* d_out, int out_size) {
    const float* logits  = (const float*)d_in[0];
    const int*   targets = (const int*)d_in[1];

    dim3 g1(W / JT, BATCH);
    k1_masks<<<g1, H>>>(targets);
    dim3 g2(RG, BATCH);
    k2_fused<<<g2, W>>>(logits);
    k3_final<<<1, 24 * 32>>>((float*)d_out);
}